// round 2
// baseline (speedup 1.0000x reference)
#include <cuda_runtime.h>
#include <math.h>

#define S_LEN 5120
#define T_LEN 1024
#define SH_LEN 4096
#define H_DIM 512
#define D_DIM 608
#define G_DIM 2048
#define LOC_N 50000
#define FC_K 1088
#define DU_DIM 64
#define NB 128   // LSTM persistent blocks

// ---------------- scratch (device globals; no allocation allowed) ----------
__device__ float g_x[S_LEN * D_DIM];
__device__ float g_pre_enc[SH_LEN * G_DIM];
__device__ float g_pre_dec[T_LEN * G_DIM];
__device__ float g_hh[SH_LEN * H_DIM];
__device__ float g_hd[T_LEN * H_DIM];
__device__ float g_attn[(size_t)T_LEN * SH_LEN];
__device__ float g_ctx[T_LEN * H_DIM];
__device__ float g_outc[T_LEN * FC_K];
__device__ float g_y[(size_t)T_LEN * LOC_N];
__device__ unsigned int g_bar_count;
__device__ volatile unsigned int g_bar_gen;

// ---------------- embedding gather ----------------
__global__ void embed_kernel(const int* __restrict__ loc, const int* __restrict__ tim,
                             const int* __restrict__ clu,
                             const float* __restrict__ el, const float* __restrict__ et,
                             const float* __restrict__ ec) {
    int s = blockIdx.x, t = threadIdx.x;
    float* xrow = &g_x[(size_t)s * D_DIM];
    if (t < 128) {
        float4 v = *(const float4*)&el[(size_t)loc[s] * 512 + t * 4];
        *(float4*)&xrow[t * 4] = v;
    } else if (t < 136) {
        int j = t - 128;
        float4 v = *(const float4*)&et[(size_t)tim[s] * 32 + j * 4];
        *(float4*)&xrow[512 + j * 4] = v;
    } else if (t < 152) {
        int j = t - 136;
        float4 v = *(const float4*)&ec[(size_t)clu[s] * 64 + j * 4];
        *(float4*)&xrow[544 + j * 4] = v;
    }
}

// ---------------- generic fp32 GEMM: C = A @ op(B) + bias1 + bias2 --------
// A: [M,K] row-major.  TRANSB=1: B is [N,K] (C=A@B^T). TRANSB=0: B is [K,N].
// M must be a multiple of 128. K a multiple of 16. N guarded (N%4==0).
template<int TRANSB>
__global__ void __launch_bounds__(256) gemm_kernel(
    const float* __restrict__ A, const float* __restrict__ B,
    float* __restrict__ C, const float* __restrict__ bias1,
    const float* __restrict__ bias2, int M, int N, int K)
{
    __shared__ float As[2][16][132];
    __shared__ float Bs[2][16][68];
    const int tid = threadIdx.x;
    const int m0 = blockIdx.y * 128;
    const int n0 = blockIdx.x * 64;
    const int tx = tid & 15, ty = tid >> 4;
    const int ar = tid >> 2;          // 0..63
    const int ak = (tid & 3) << 2;    // 0,4,8,12
    const int bk = tid >> 4;          // 0..15 (NN)
    const int bn = (tid & 15) << 2;   // 0..60 (NN)

    float acc[8][4];
#pragma unroll
    for (int i = 0; i < 8; i++)
#pragma unroll
        for (int j = 0; j < 4; j++) acc[i][j] = 0.f;

    float4 rA0, rA1, rB;
    const int KT = K >> 4;

    // prologue: tile 0
    rA0 = *(const float4*)&A[(size_t)(m0 + ar) * K + ak];
    rA1 = *(const float4*)&A[(size_t)(m0 + ar + 64) * K + ak];
    if (TRANSB) {
        if (n0 + ar < N) rB = *(const float4*)&B[(size_t)(n0 + ar) * K + ak];
        else rB = make_float4(0.f, 0.f, 0.f, 0.f);
    } else {
        if (n0 + bn < N) rB = *(const float4*)&B[(size_t)bk * N + n0 + bn];
        else rB = make_float4(0.f, 0.f, 0.f, 0.f);
    }
    As[0][ak + 0][ar] = rA0.x; As[0][ak + 1][ar] = rA0.y;
    As[0][ak + 2][ar] = rA0.z; As[0][ak + 3][ar] = rA0.w;
    As[0][ak + 0][ar + 64] = rA1.x; As[0][ak + 1][ar + 64] = rA1.y;
    As[0][ak + 2][ar + 64] = rA1.z; As[0][ak + 3][ar + 64] = rA1.w;
    if (TRANSB) {
        Bs[0][ak + 0][ar] = rB.x; Bs[0][ak + 1][ar] = rB.y;
        Bs[0][ak + 2][ar] = rB.z; Bs[0][ak + 3][ar] = rB.w;
    } else {
        *(float4*)&Bs[0][bk][bn] = rB;
    }
    __syncthreads();

    for (int kt = 0; kt < KT; kt++) {
        const int cur = kt & 1;
        if (kt + 1 < KT) {
            const int k0 = (kt + 1) << 4;
            rA0 = *(const float4*)&A[(size_t)(m0 + ar) * K + k0 + ak];
            rA1 = *(const float4*)&A[(size_t)(m0 + ar + 64) * K + k0 + ak];
            if (TRANSB) {
                if (n0 + ar < N) rB = *(const float4*)&B[(size_t)(n0 + ar) * K + k0 + ak];
                else rB = make_float4(0.f, 0.f, 0.f, 0.f);
            } else {
                if (n0 + bn < N) rB = *(const float4*)&B[(size_t)(k0 + bk) * N + n0 + bn];
                else rB = make_float4(0.f, 0.f, 0.f, 0.f);
            }
        }
#pragma unroll
        for (int kk = 0; kk < 16; kk++) {
            float4 a0 = *(const float4*)&As[cur][kk][ty * 8];
            float4 a1 = *(const float4*)&As[cur][kk][ty * 8 + 4];
            float4 b  = *(const float4*)&Bs[cur][kk][tx * 4];
            float av[8] = {a0.x, a0.y, a0.z, a0.w, a1.x, a1.y, a1.z, a1.w};
            float bv[4] = {b.x, b.y, b.z, b.w};
#pragma unroll
            for (int i = 0; i < 8; i++)
#pragma unroll
                for (int j = 0; j < 4; j++) acc[i][j] += av[i] * bv[j];
        }
        if (kt + 1 < KT) {
            const int nb = cur ^ 1;
            As[nb][ak + 0][ar] = rA0.x; As[nb][ak + 1][ar] = rA0.y;
            As[nb][ak + 2][ar] = rA0.z; As[nb][ak + 3][ar] = rA0.w;
            As[nb][ak + 0][ar + 64] = rA1.x; As[nb][ak + 1][ar + 64] = rA1.y;
            As[nb][ak + 2][ar + 64] = rA1.z; As[nb][ak + 3][ar + 64] = rA1.w;
            if (TRANSB) {
                Bs[nb][ak + 0][ar] = rB.x; Bs[nb][ak + 1][ar] = rB.y;
                Bs[nb][ak + 2][ar] = rB.z; Bs[nb][ak + 3][ar] = rB.w;
            } else {
                *(float4*)&Bs[nb][bk][bn] = rB;
            }
            __syncthreads();
        }
    }

    const int n = n0 + tx * 4;
    if (n < N) {
        float b0 = 0.f, b1 = 0.f, b2 = 0.f, b3 = 0.f;
        if (bias1) { b0 += bias1[n]; b1 += bias1[n + 1]; b2 += bias1[n + 2]; b3 += bias1[n + 3]; }
        if (bias2) { b0 += bias2[n]; b1 += bias2[n + 1]; b2 += bias2[n + 2]; b3 += bias2[n + 3]; }
#pragma unroll
        for (int i = 0; i < 8; i++) {
            float4 o;
            o.x = acc[i][0] + b0; o.y = acc[i][1] + b1;
            o.z = acc[i][2] + b2; o.w = acc[i][3] + b3;
            *(float4*)&C[(size_t)(m0 + ty * 8 + i) * N + n] = o;
        }
    }
}

// ---------------- persistent LSTM with grid barrier ----------------
__device__ __forceinline__ float sigmoidf_(float x) { return 1.f / (1.f + expf(-x)); }

__global__ void bar_reset_kernel() { g_bar_count = 0u; g_bar_gen = 0u; }

// grid = NB blocks x 256 threads. Block b owns hidden units [4b, 4b+4).
// pre: [T, 2048] = x@Wih^T + bih + bhh.  hist: [T, 512] output h sequence.
__global__ void __launch_bounds__(256) lstm_kernel(
    const float* __restrict__ pre, const float* __restrict__ Whh,
    float* __restrict__ hist, int T)
{
    __shared__ float Ws[16][H_DIM];
    __shared__ float hs[H_DIM];
    __shared__ float gs[16];
    __shared__ float ps[16];
    __shared__ float cs[4];
    const int b = blockIdx.x;
    const int tid = threadIdx.x;
    const int lane = tid & 31;
    const int warp = tid >> 5;

    for (int r = 0; r < 16; r++) {
        int grow = (r >> 2) * H_DIM + b * 4 + (r & 3);
        for (int k = tid; k < H_DIM; k += 256)
            Ws[r][k] = Whh[(size_t)grow * H_DIM + k];
    }
    if (tid < 4) cs[tid] = 0.f;

    unsigned int gen = 0;
    const int r0 = warp * 2, r1 = r0 + 1;

    for (int t = 0; t < T; t++) {
        if (t == 0) {
            hs[2 * tid] = 0.f; hs[2 * tid + 1] = 0.f;
        } else {
            float2 hv = __ldcg((const float2*)&hist[(size_t)(t - 1) * H_DIM + 2 * tid]);
            hs[2 * tid] = hv.x; hs[2 * tid + 1] = hv.y;
        }
        if (tid < 16)
            ps[tid] = pre[(size_t)t * G_DIM + (tid >> 2) * H_DIM + b * 4 + (tid & 3)];
        __syncthreads();

        float a0 = 0.f, a1 = 0.f;
#pragma unroll
        for (int j = 0; j < 16; j++) {
            float hv = hs[lane + 32 * j];
            a0 += Ws[r0][lane + 32 * j] * hv;
            a1 += Ws[r1][lane + 32 * j] * hv;
        }
#pragma unroll
        for (int o = 16; o > 0; o >>= 1) {
            a0 += __shfl_down_sync(0xffffffffu, a0, o);
            a1 += __shfl_down_sync(0xffffffffu, a1, o);
        }
        if (lane == 0) { gs[r0] = a0 + ps[r0]; gs[r1] = a1 + ps[r1]; }
        __syncthreads();

        if (tid < 4) {
            float ig = sigmoidf_(gs[tid]);
            float fg = sigmoidf_(gs[4 + tid]);
            float gg = tanhf(gs[8 + tid]);
            float og = sigmoidf_(gs[12 + tid]);
            float c = fg * cs[tid] + ig * gg;
            cs[tid] = c;
            float h = og * tanhf(c);
            __stcg(&hist[(size_t)t * H_DIM + b * 4 + tid], h);
        }

        // grid barrier (all NB blocks co-resident: NB <= 148 SMs, 1 block/SM)
        __syncthreads();
        if (tid == 0) {
            __threadfence();
            unsigned int target = gen + 1;
            if (atomicAdd(&g_bar_count, 1u) == NB - 1) {
                atomicExch(&g_bar_count, 0u);
                __threadfence();
                g_bar_gen = target;
            } else {
                while (g_bar_gen < target) { }
            }
            __threadfence();
        }
        gen++;
        __syncthreads();
    }
}

// ---------------- reductions ----------------
__device__ __forceinline__ float block_max_256(float v, float* red) {
#pragma unroll
    for (int o = 16; o > 0; o >>= 1) v = fmaxf(v, __shfl_xor_sync(0xffffffffu, v, o));
    if ((threadIdx.x & 31) == 0) red[threadIdx.x >> 5] = v;
    __syncthreads();
    if (threadIdx.x < 32) {
        float x = (threadIdx.x < 8) ? red[threadIdx.x] : -1e30f;
#pragma unroll
        for (int o = 4; o > 0; o >>= 1) x = fmaxf(x, __shfl_xor_sync(0xffffffffu, x, o));
        if (threadIdx.x == 0) red[0] = x;
    }
    __syncthreads();
    float r = red[0];
    __syncthreads();
    return r;
}

__device__ __forceinline__ float block_sum_256(float v, float* red) {
#pragma unroll
    for (int o = 16; o > 0; o >>= 1) v += __shfl_xor_sync(0xffffffffu, v, o);
    if ((threadIdx.x & 31) == 0) red[threadIdx.x >> 5] = v;
    __syncthreads();
    if (threadIdx.x < 32) {
        float x = (threadIdx.x < 8) ? red[threadIdx.x] : 0.f;
#pragma unroll
        for (int o = 4; o > 0; o >>= 1) x += __shfl_xor_sync(0xffffffffu, x, o);
        if (threadIdx.x == 0) red[0] = x;
    }
    __syncthreads();
    float r = red[0];
    __syncthreads();
    return r;
}

// softmax in place over rows of g_attn [T_LEN, SH_LEN]
__global__ void __launch_bounds__(256) softmax_kernel() {
    __shared__ float red[8];
    const int row = blockIdx.x, tid = threadIdx.x;
    float* X = &g_attn[(size_t)row * SH_LEN];
    float v[16];
    float m = -1e30f;
#pragma unroll
    for (int j = 0; j < 16; j++) { v[j] = X[tid + j * 256]; m = fmaxf(m, v[j]); }
    m = block_max_256(m, red);
    float s = 0.f;
#pragma unroll
    for (int j = 0; j < 16; j++) { v[j] = expf(v[j] - m); s += v[j]; }
    s = block_sum_256(s, red);
    float inv = 1.f / s;
#pragma unroll
    for (int j = 0; j < 16; j++) X[tid + j * 256] = v[j] * inv;
}

// log_softmax over rows of g_y [T_LEN, LOC_N] -> out
__global__ void __launch_bounds__(256) logsoftmax_kernel(float* __restrict__ out) {
    __shared__ float red[8];
    const int row = blockIdx.x, tid = threadIdx.x;
    const float* Y = &g_y[(size_t)row * LOC_N];
    float* O = &out[(size_t)row * LOC_N];
    float m = -1e30f;
    for (int c = tid; c < LOC_N; c += 256) m = fmaxf(m, Y[c]);
    m = block_max_256(m, red);
    float s = 0.f;
    for (int c = tid; c < LOC_N; c += 256) s += expf(Y[c] - m);
    s = block_sum_256(s, red);
    float ls = m + logf(s);
    for (int c = tid; c < LOC_N; c += 256) O[c] = Y[c] - ls;
}

// concat [hd | ctx | uid_emb] -> g_outc [T_LEN, FC_K]
__global__ void concat_kernel(const float* __restrict__ emb_uid, const int* __restrict__ uid) {
    int row = blockIdx.x, t = threadIdx.x;
    float4 v;
    if (t < 128)       v = *(const float4*)&g_hd[(size_t)row * H_DIM + t * 4];
    else if (t < 256)  v = *(const float4*)&g_ctx[(size_t)row * H_DIM + (t - 128) * 4];
    else               v = *(const float4*)&emb_uid[(size_t)uid[0] * DU_DIM + (t - 256) * 4];
    *(float4*)&g_outc[(size_t)row * FC_K + t * 4] = v;
}

// ---------------- host ----------------
extern "C" void kernel_launch(void* const* d_in, const int* in_sizes, int n_in,
                              void* d_out, int out_size) {
    const int* loc = (const int*)d_in[0];
    const int* tim = (const int*)d_in[1];
    const int* clu = (const int*)d_in[2];
    const int* uid = (const int*)d_in[3];
    // d_in[4] = target_len (compile-time 1024)
    const float* emb_loc = (const float*)d_in[5];
    const float* emb_tim = (const float*)d_in[6];
    const float* emb_clu = (const float*)d_in[7];
    const float* emb_uid = (const float*)d_in[8];
    const float* eWih = (const float*)d_in[9];
    const float* eWhh = (const float*)d_in[10];
    const float* ebih = (const float*)d_in[11];
    const float* ebhh = (const float*)d_in[12];
    const float* dWih = (const float*)d_in[13];
    const float* dWhh = (const float*)d_in[14];
    const float* dbih = (const float*)d_in[15];
    const float* dbhh = (const float*)d_in[16];
    const float* fcW = (const float*)d_in[17];
    const float* fcb = (const float*)d_in[18];
    float* out = (float*)d_out;

    float *px, *ppe, *ppd, *phh, *phd, *pat, *pcx, *pot, *py;
    cudaGetSymbolAddress((void**)&px,  g_x);
    cudaGetSymbolAddress((void**)&ppe, g_pre_enc);
    cudaGetSymbolAddress((void**)&ppd, g_pre_dec);
    cudaGetSymbolAddress((void**)&phh, g_hh);
    cudaGetSymbolAddress((void**)&phd, g_hd);
    cudaGetSymbolAddress((void**)&pat, g_attn);
    cudaGetSymbolAddress((void**)&pcx, g_ctx);
    cudaGetSymbolAddress((void**)&pot, g_outc);
    cudaGetSymbolAddress((void**)&py,  g_y);

    // 1. embed
    embed_kernel<<<S_LEN, 152>>>(loc, tim, clu, emb_loc, emb_tim, emb_clu);
    // 2. input projections (include both biases)
    gemm_kernel<1><<<dim3(G_DIM / 64, SH_LEN / 128), 256>>>(px, eWih, ppe, ebih, ebhh,
                                                            SH_LEN, G_DIM, D_DIM);
    gemm_kernel<1><<<dim3(G_DIM / 64, T_LEN / 128), 256>>>(px + (size_t)SH_LEN * D_DIM, dWih,
                                                           ppd, dbih, dbhh, T_LEN, G_DIM, D_DIM);
    // 3. encoder LSTM
    bar_reset_kernel<<<1, 1>>>();
    lstm_kernel<<<NB, 256>>>(ppe, eWhh, phh, SH_LEN);
    // 4. decoder LSTM
    bar_reset_kernel<<<1, 1>>>();
    lstm_kernel<<<NB, 256>>>(ppd, dWhh, phd, T_LEN);
    // 5. attention scores = hd @ hh^T
    gemm_kernel<1><<<dim3(SH_LEN / 64, T_LEN / 128), 256>>>(phd, phh, pat, nullptr, nullptr,
                                                            T_LEN, SH_LEN, H_DIM);
    // 6. softmax rows
    softmax_kernel<<<T_LEN, 256>>>();
    // 7. context = attn @ hh
    gemm_kernel<0><<<dim3(H_DIM / 64, T_LEN / 128), 256>>>(pat, phh, pcx, nullptr, nullptr,
                                                           T_LEN, H_DIM, SH_LEN);
    // 8. concat
    concat_kernel<<<T_LEN, 272>>>(emb_uid, uid);
    // 9. FC: y = outc @ fcW^T + fcb   (N=50000 guarded: 782 tiles)
    gemm_kernel<1><<<dim3((LOC_N + 63) / 64, T_LEN / 128), 256>>>(pot, fcW, py, fcb, nullptr,
                                                                  T_LEN, LOC_N, FC_K);
    // 10. log_softmax -> output
    logsoftmax_kernel<<<T_LEN, 256>>>(out);
}

// round 3
// speedup vs baseline: 1.1587x; 1.1587x over previous
#include <cuda_runtime.h>
#include <cuda_bf16.h>
#include <math.h>
#include <stdint.h>

#define S_LEN 5120
#define T_LEN 1024
#define SH_LEN 4096
#define H_DIM 512
#define D_DIM 608
#define G_DIM 2048
#define LOC_N 50000
#define FC_K 1088
#define DU_DIM 64
#define NB 128   // LSTM persistent blocks

// ---------------- scratch (device globals; no allocation allowed) ----------
__device__ float g_x[S_LEN * D_DIM];
__device__ float g_pre_enc[SH_LEN * G_DIM];
__device__ float g_pre_dec[T_LEN * G_DIM];
__device__ float g_hh[SH_LEN * H_DIM];
__device__ float g_hd[T_LEN * H_DIM];
__device__ float g_attn[(size_t)T_LEN * SH_LEN];
__device__ float g_ctx[T_LEN * H_DIM];
__device__ float g_y[(size_t)T_LEN * LOC_N];
__device__ unsigned int g_bar_count;
__device__ volatile unsigned int g_bar_gen;

// bf16 operand buffers
__device__ __nv_bfloat16 g_xb[S_LEN * D_DIM];
__device__ __nv_bfloat16 g_wihb_e[G_DIM * D_DIM];
__device__ __nv_bfloat16 g_wihb_d[G_DIM * D_DIM];
__device__ __nv_bfloat16 g_fcWb[(size_t)LOC_N * FC_K];
__device__ __nv_bfloat16 g_hhb[SH_LEN * H_DIM];
__device__ __nv_bfloat16 g_hdb[T_LEN * H_DIM];
__device__ __nv_bfloat16 g_hhTb[H_DIM * SH_LEN];
__device__ __nv_bfloat16 g_attnb[(size_t)T_LEN * SH_LEN];
__device__ __nv_bfloat16 g_outb[T_LEN * FC_K];

// ---------------- embedding gather ----------------
__global__ void embed_kernel(const int* __restrict__ loc, const int* __restrict__ tim,
                             const int* __restrict__ clu,
                             const float* __restrict__ el, const float* __restrict__ et,
                             const float* __restrict__ ec) {
    int s = blockIdx.x, t = threadIdx.x;
    float* xrow = &g_x[(size_t)s * D_DIM];
    if (t < 128) {
        float4 v = *(const float4*)&el[(size_t)loc[s] * 512 + t * 4];
        *(float4*)&xrow[t * 4] = v;
    } else if (t < 136) {
        int j = t - 128;
        float4 v = *(const float4*)&et[(size_t)tim[s] * 32 + j * 4];
        *(float4*)&xrow[512 + j * 4] = v;
    } else if (t < 152) {
        int j = t - 136;
        float4 v = *(const float4*)&ec[(size_t)clu[s] * 64 + j * 4];
        *(float4*)&xrow[544 + j * 4] = v;
    }
}

// ---------------- fp32 -> bf16 conversion (8 elems/thread) ----------------
__global__ void f2b_kernel(const float* __restrict__ in, __nv_bfloat16* __restrict__ out,
                           int n) {
    int i = (blockIdx.x * blockDim.x + threadIdx.x) * 8;
    if (i < n) {
        float4 v0 = *(const float4*)&in[i];
        float4 v1 = *(const float4*)&in[i + 4];
        __nv_bfloat162 o[4];
        o[0] = __float22bfloat162_rn(make_float2(v0.x, v0.y));
        o[1] = __float22bfloat162_rn(make_float2(v0.z, v0.w));
        o[2] = __float22bfloat162_rn(make_float2(v1.x, v1.y));
        o[3] = __float22bfloat162_rn(make_float2(v1.z, v1.w));
        *(int4*)&out[i] = *(int4*)o;
    }
}

// transpose fp32 [R,C] -> bf16 [C,R]
__global__ void transpose_b_kernel(const float* __restrict__ in,
                                   __nv_bfloat16* __restrict__ out, int R, int C) {
    __shared__ float tile[32][33];
    int x = blockIdx.x * 32 + threadIdx.x;
    int y = blockIdx.y * 32 + threadIdx.y;
#pragma unroll
    for (int j = 0; j < 32; j += 8)
        tile[threadIdx.y + j][threadIdx.x] = in[(size_t)(y + j) * C + x];
    __syncthreads();
    int ox = blockIdx.y * 32 + threadIdx.x;
    int oy = blockIdx.x * 32 + threadIdx.y;
#pragma unroll
    for (int j = 0; j < 32; j += 8)
        out[(size_t)(oy + j) * R + ox] = __float2bfloat16(tile[threadIdx.x][threadIdx.y + j]);
}

// ---------------- bf16 tensor-core GEMM: C = A @ B^T + bias -------------
// A: [M,K] bf16 row-major. B: [N,K] bf16 row-major. C: [M,N] fp32.
// M % 128 == 0, K % 32 == 0, N arbitrary (guarded).
__device__ __forceinline__ void ldsm4(uint32_t& r0, uint32_t& r1, uint32_t& r2,
                                      uint32_t& r3, uint32_t a) {
    asm volatile("ldmatrix.sync.aligned.m8n8.x4.shared.b16 {%0,%1,%2,%3}, [%4];"
                 : "=r"(r0), "=r"(r1), "=r"(r2), "=r"(r3) : "r"(a));
}
__device__ __forceinline__ void mma16816(float* c, const uint32_t* a, const uint32_t* b) {
    asm volatile(
        "mma.sync.aligned.m16n8k16.row.col.f32.bf16.bf16.f32 "
        "{%0,%1,%2,%3},{%4,%5,%6,%7},{%8,%9},{%0,%1,%2,%3};"
        : "+f"(c[0]), "+f"(c[1]), "+f"(c[2]), "+f"(c[3])
        : "r"(a[0]), "r"(a[1]), "r"(a[2]), "r"(a[3]), "r"(b[0]), "r"(b[1]));
}

__global__ void __launch_bounds__(256) gemm_tc(
    const __nv_bfloat16* __restrict__ A, const __nv_bfloat16* __restrict__ B,
    float* __restrict__ C, const float* __restrict__ bias1,
    const float* __restrict__ bias2, int M, int N, int K)
{
    __shared__ __nv_bfloat16 As[2][128][40];
    __shared__ __nv_bfloat16 Bs[2][128][40];
    const int tid = threadIdx.x, lane = tid & 31, warp = tid >> 5;
    const int wm = warp & 1, wn = warp >> 1;   // 2 x 4 warp grid
    const int m0 = blockIdx.y * 128, n0 = blockIdx.x * 128;
    const int lr = tid >> 2;          // 0..63
    const int lc = (tid & 3) << 3;    // 0,8,16,24
    const int grp = lane >> 3, lrr = lane & 7;

    float acc[4][4][4];
#pragma unroll
    for (int i = 0; i < 4; i++)
#pragma unroll
        for (int j = 0; j < 4; j++)
#pragma unroll
            for (int r = 0; r < 4; r++) acc[i][j][r] = 0.f;

    int4 ra0, ra1, rb0, rb1;
    const int KT = K >> 5;
    const int4 zero4 = make_int4(0, 0, 0, 0);

    // prologue: global load tile 0
    {
        const __nv_bfloat16* Ap = A + (size_t)(m0 + lr) * K + lc;
        ra0 = *(const int4*)Ap;
        ra1 = *(const int4*)(Ap + (size_t)64 * K);
        int nr0 = n0 + lr, nr1 = nr0 + 64;
        rb0 = (nr0 < N) ? *(const int4*)(B + (size_t)nr0 * K + lc) : zero4;
        rb1 = (nr1 < N) ? *(const int4*)(B + (size_t)nr1 * K + lc) : zero4;
    }
    *(int4*)&As[0][lr][lc] = ra0;
    *(int4*)&As[0][lr + 64][lc] = ra1;
    *(int4*)&Bs[0][lr][lc] = rb0;
    *(int4*)&Bs[0][lr + 64][lc] = rb1;
    __syncthreads();

    for (int kt = 0; kt < KT; kt++) {
        const int buf = kt & 1;
        if (kt + 1 < KT) {
            const int k0 = (kt + 1) << 5;
            const __nv_bfloat16* Ap = A + (size_t)(m0 + lr) * K + k0 + lc;
            ra0 = *(const int4*)Ap;
            ra1 = *(const int4*)(Ap + (size_t)64 * K);
            int nr0 = n0 + lr, nr1 = nr0 + 64;
            rb0 = (nr0 < N) ? *(const int4*)(B + (size_t)nr0 * K + k0 + lc) : zero4;
            rb1 = (nr1 < N) ? *(const int4*)(B + (size_t)nr1 * K + k0 + lc) : zero4;
        }
#pragma unroll
        for (int kk = 0; kk < 2; kk++) {
            const int kb = kk << 4;
            uint32_t af[4][4], bf[4][2];
#pragma unroll
            for (int mt = 0; mt < 4; mt++) {
                int row = wm * 64 + mt * 16 + ((grp & 1) << 3) + lrr;
                int col = kb + ((grp >> 1) << 3);
                ldsm4(af[mt][0], af[mt][1], af[mt][2], af[mt][3],
                      (uint32_t)__cvta_generic_to_shared(&As[buf][row][col]));
            }
#pragma unroll
            for (int nt2 = 0; nt2 < 2; nt2++) {
                int row = wn * 32 + nt2 * 16 + ((grp >> 1) << 3) + lrr;
                int col = kb + ((grp & 1) << 3);
                uint32_t r0, r1, r2, r3;
                ldsm4(r0, r1, r2, r3,
                      (uint32_t)__cvta_generic_to_shared(&Bs[buf][row][col]));
                bf[nt2 * 2][0] = r0; bf[nt2 * 2][1] = r1;
                bf[nt2 * 2 + 1][0] = r2; bf[nt2 * 2 + 1][1] = r3;
            }
#pragma unroll
            for (int mt = 0; mt < 4; mt++)
#pragma unroll
                for (int nt = 0; nt < 4; nt++)
                    mma16816(acc[mt][nt], af[mt], bf[nt]);
        }
        if (kt + 1 < KT) {
            const int nb = buf ^ 1;
            *(int4*)&As[nb][lr][lc] = ra0;
            *(int4*)&As[nb][lr + 64][lc] = ra1;
            *(int4*)&Bs[nb][lr][lc] = rb0;
            *(int4*)&Bs[nb][lr + 64][lc] = rb1;
            __syncthreads();
        }
    }

    // epilogue
#pragma unroll
    for (int nt = 0; nt < 4; nt++) {
        int col = n0 + wn * 32 + nt * 8 + ((lane & 3) << 1);
        if (col >= N) continue;
        float b0 = 0.f, b1 = 0.f;
        if (bias1) { b0 += bias1[col]; b1 += bias1[col + 1]; }
        if (bias2) { b0 += bias2[col]; b1 += bias2[col + 1]; }
#pragma unroll
        for (int mt = 0; mt < 4; mt++) {
            int row = m0 + wm * 64 + mt * 16 + (lane >> 2);
            float2 v0 = make_float2(acc[mt][nt][0] + b0, acc[mt][nt][1] + b1);
            float2 v1 = make_float2(acc[mt][nt][2] + b0, acc[mt][nt][3] + b1);
            *(float2*)&C[(size_t)row * N + col] = v0;
            *(float2*)&C[(size_t)(row + 8) * N + col] = v1;
        }
    }
}

// ---------------- persistent LSTM with grid barrier ----------------
__device__ __forceinline__ float sigmoidf_(float x) { return 1.f / (1.f + expf(-x)); }

__global__ void bar_reset_kernel() { g_bar_count = 0u; g_bar_gen = 0u; }

__global__ void __launch_bounds__(256) lstm_kernel(
    const float* __restrict__ pre, const float* __restrict__ Whh,
    float* __restrict__ hist, int T)
{
    __shared__ float Ws[16][H_DIM];
    __shared__ float hs[H_DIM];
    __shared__ float gs[16];
    __shared__ float ps[16];
    __shared__ float cs[4];
    const int b = blockIdx.x;
    const int tid = threadIdx.x;
    const int lane = tid & 31;
    const int warp = tid >> 5;

    for (int r = 0; r < 16; r++) {
        int grow = (r >> 2) * H_DIM + b * 4 + (r & 3);
        for (int k = tid; k < H_DIM; k += 256)
            Ws[r][k] = Whh[(size_t)grow * H_DIM + k];
    }
    if (tid < 4) cs[tid] = 0.f;

    unsigned int gen = 0;
    const int r0 = warp * 2, r1 = r0 + 1;

    for (int t = 0; t < T; t++) {
        if (t == 0) {
            hs[2 * tid] = 0.f; hs[2 * tid + 1] = 0.f;
        } else {
            float2 hv = __ldcg((const float2*)&hist[(size_t)(t - 1) * H_DIM + 2 * tid]);
            hs[2 * tid] = hv.x; hs[2 * tid + 1] = hv.y;
        }
        if (tid < 16)
            ps[tid] = pre[(size_t)t * G_DIM + (tid >> 2) * H_DIM + b * 4 + (tid & 3)];
        __syncthreads();

        float a0 = 0.f, a1 = 0.f;
#pragma unroll
        for (int j = 0; j < 16; j++) {
            float hv = hs[lane + 32 * j];
            a0 += Ws[r0][lane + 32 * j] * hv;
            a1 += Ws[r1][lane + 32 * j] * hv;
        }
#pragma unroll
        for (int o = 16; o > 0; o >>= 1) {
            a0 += __shfl_down_sync(0xffffffffu, a0, o);
            a1 += __shfl_down_sync(0xffffffffu, a1, o);
        }
        if (lane == 0) { gs[r0] = a0 + ps[r0]; gs[r1] = a1 + ps[r1]; }
        __syncthreads();

        if (tid < 4) {
            float ig = sigmoidf_(gs[tid]);
            float fg = sigmoidf_(gs[4 + tid]);
            float gg = tanhf(gs[8 + tid]);
            float og = sigmoidf_(gs[12 + tid]);
            float c = fg * cs[tid] + ig * gg;
            cs[tid] = c;
            float h = og * tanhf(c);
            __stcg(&hist[(size_t)t * H_DIM + b * 4 + tid], h);
        }

        __syncthreads();
        if (tid == 0) {
            __threadfence();
            unsigned int target = gen + 1;
            if (atomicAdd(&g_bar_count, 1u) == NB - 1) {
                atomicExch(&g_bar_count, 0u);
                __threadfence();
                g_bar_gen = target;
            } else {
                while (g_bar_gen < target) { }
            }
            __threadfence();
        }
        gen++;
        __syncthreads();
    }
}

// ---------------- reductions ----------------
__device__ __forceinline__ float block_max_256(float v, float* red) {
#pragma unroll
    for (int o = 16; o > 0; o >>= 1) v = fmaxf(v, __shfl_xor_sync(0xffffffffu, v, o));
    if ((threadIdx.x & 31) == 0) red[threadIdx.x >> 5] = v;
    __syncthreads();
    if (threadIdx.x < 32) {
        float x = (threadIdx.x < 8) ? red[threadIdx.x] : -1e30f;
#pragma unroll
        for (int o = 4; o > 0; o >>= 1) x = fmaxf(x, __shfl_xor_sync(0xffffffffu, x, o));
        if (threadIdx.x == 0) red[0] = x;
    }
    __syncthreads();
    float r = red[0];
    __syncthreads();
    return r;
}

__device__ __forceinline__ float block_sum_256(float v, float* red) {
#pragma unroll
    for (int o = 16; o > 0; o >>= 1) v += __shfl_xor_sync(0xffffffffu, v, o);
    if ((threadIdx.x & 31) == 0) red[threadIdx.x >> 5] = v;
    __syncthreads();
    if (threadIdx.x < 32) {
        float x = (threadIdx.x < 8) ? red[threadIdx.x] : 0.f;
#pragma unroll
        for (int o = 4; o > 0; o >>= 1) x += __shfl_xor_sync(0xffffffffu, x, o);
        if (threadIdx.x == 0) red[0] = x;
    }
    __syncthreads();
    float r = red[0];
    __syncthreads();
    return r;
}

// softmax over rows of g_attn [T_LEN, SH_LEN] -> bf16 g_attnb
__global__ void __launch_bounds__(256) softmax_kernel() {
    __shared__ float red[8];
    const int row = blockIdx.x, tid = threadIdx.x;
    const float* X = &g_attn[(size_t)row * SH_LEN];
    __nv_bfloat16* O = &g_attnb[(size_t)row * SH_LEN];
    float v[16];
    float m = -1e30f;
#pragma unroll
    for (int j = 0; j < 16; j++) { v[j] = X[tid + j * 256]; m = fmaxf(m, v[j]); }
    m = block_max_256(m, red);
    float s = 0.f;
#pragma unroll
    for (int j = 0; j < 16; j++) { v[j] = expf(v[j] - m); s += v[j]; }
    s = block_sum_256(s, red);
    float inv = 1.f / s;
#pragma unroll
    for (int j = 0; j < 16; j++) O[tid + j * 256] = __float2bfloat16(v[j] * inv);
}

// log_softmax over rows of g_y [T_LEN, LOC_N] -> out
__global__ void __launch_bounds__(256) logsoftmax_kernel(float* __restrict__ out) {
    __shared__ float red[8];
    const int row = blockIdx.x, tid = threadIdx.x;
    const float* Y = &g_y[(size_t)row * LOC_N];
    float* O = &out[(size_t)row * LOC_N];
    float m = -1e30f;
    for (int c = tid; c < LOC_N; c += 256) m = fmaxf(m, Y[c]);
    m = block_max_256(m, red);
    float s = 0.f;
    for (int c = tid; c < LOC_N; c += 256) s += expf(Y[c] - m);
    s = block_sum_256(s, red);
    float ls = m + logf(s);
    for (int c = tid; c < LOC_N; c += 256) O[c] = Y[c] - ls;
}

// concat [hd | ctx | uid_emb] -> g_outb bf16 [T_LEN, FC_K]
__global__ void concat_kernel(const float* __restrict__ emb_uid, const int* __restrict__ uid) {
    int row = blockIdx.x, t = threadIdx.x;
    float4 v;
    if (t < 128)       v = *(const float4*)&g_hd[(size_t)row * H_DIM + t * 4];
    else if (t < 256)  v = *(const float4*)&g_ctx[(size_t)row * H_DIM + (t - 128) * 4];
    else               v = *(const float4*)&emb_uid[(size_t)uid[0] * DU_DIM + (t - 256) * 4];
    __nv_bfloat162 o[2];
    o[0] = __float22bfloat162_rn(make_float2(v.x, v.y));
    o[1] = __float22bfloat162_rn(make_float2(v.z, v.w));
    *(uint2*)&g_outb[(size_t)row * FC_K + t * 4] = *(uint2*)o;
}

// ---------------- host ----------------
extern "C" void kernel_launch(void* const* d_in, const int* in_sizes, int n_in,
                              void* d_out, int out_size) {
    const int* loc = (const int*)d_in[0];
    const int* tim = (const int*)d_in[1];
    const int* clu = (const int*)d_in[2];
    const int* uid = (const int*)d_in[3];
    const float* emb_loc = (const float*)d_in[5];
    const float* emb_tim = (const float*)d_in[6];
    const float* emb_clu = (const float*)d_in[7];
    const float* emb_uid = (const float*)d_in[8];
    const float* eWih = (const float*)d_in[9];
    const float* eWhh = (const float*)d_in[10];
    const float* ebih = (const float*)d_in[11];
    const float* ebhh = (const float*)d_in[12];
    const float* dWih = (const float*)d_in[13];
    const float* dWhh = (const float*)d_in[14];
    const float* dbih = (const float*)d_in[15];
    const float* dbhh = (const float*)d_in[16];
    const float* fcW = (const float*)d_in[17];
    const float* fcb = (const float*)d_in[18];
    float* out = (float*)d_out;

    float *px, *ppe, *ppd, *phh, *phd, *pat, *pcx, *py;
    cudaGetSymbolAddress((void**)&px,  g_x);
    cudaGetSymbolAddress((void**)&ppe, g_pre_enc);
    cudaGetSymbolAddress((void**)&ppd, g_pre_dec);
    cudaGetSymbolAddress((void**)&phh, g_hh);
    cudaGetSymbolAddress((void**)&phd, g_hd);
    cudaGetSymbolAddress((void**)&pat, g_attn);
    cudaGetSymbolAddress((void**)&pcx, g_ctx);
    cudaGetSymbolAddress((void**)&py,  g_y);
    __nv_bfloat16 *pxb, *pweb, *pwdb, *pfcb, *phhb, *phdb, *phhTb, *patb, *potb;
    cudaGetSymbolAddress((void**)&pxb,   g_xb);
    cudaGetSymbolAddress((void**)&pweb,  g_wihb_e);
    cudaGetSymbolAddress((void**)&pwdb,  g_wihb_d);
    cudaGetSymbolAddress((void**)&pfcb,  g_fcWb);
    cudaGetSymbolAddress((void**)&phhb,  g_hhb);
    cudaGetSymbolAddress((void**)&phdb,  g_hdb);
    cudaGetSymbolAddress((void**)&phhTb, g_hhTb);
    cudaGetSymbolAddress((void**)&patb,  g_attnb);
    cudaGetSymbolAddress((void**)&potb,  g_outb);

    // 1. embed + conversions
    embed_kernel<<<S_LEN, 152>>>(loc, tim, clu, emb_loc, emb_tim, emb_clu);
    f2b_kernel<<<(S_LEN * D_DIM / 8 + 255) / 256, 256>>>(px, pxb, S_LEN * D_DIM);
    f2b_kernel<<<(G_DIM * D_DIM / 8 + 255) / 256, 256>>>(eWih, pweb, G_DIM * D_DIM);
    f2b_kernel<<<(G_DIM * D_DIM / 8 + 255) / 256, 256>>>(dWih, pwdb, G_DIM * D_DIM);
    f2b_kernel<<<(LOC_N * FC_K / 8 + 255) / 256, 256>>>(fcW, pfcb, LOC_N * FC_K);

    // 2. input projections (bf16 TC), both biases folded in
    gemm_tc<<<dim3(G_DIM / 128, SH_LEN / 128), 256>>>(pxb, pweb, ppe, ebih, ebhh,
                                                      SH_LEN, G_DIM, D_DIM);
    gemm_tc<<<dim3(G_DIM / 128, T_LEN / 128), 256>>>(pxb + (size_t)SH_LEN * D_DIM, pwdb,
                                                     ppd, dbih, dbhh, T_LEN, G_DIM, D_DIM);
    // 3/4. LSTMs (fp32)
    bar_reset_kernel<<<1, 1>>>();
    lstm_kernel<<<NB, 256>>>(ppe, eWhh, phh, SH_LEN);
    bar_reset_kernel<<<1, 1>>>();
    lstm_kernel<<<NB, 256>>>(ppd, dWhh, phd, T_LEN);

    // 5. convert hidden states to bf16 (+transposed copy of hh)
    f2b_kernel<<<(SH_LEN * H_DIM / 8 + 255) / 256, 256>>>(phh, phhb, SH_LEN * H_DIM);
    f2b_kernel<<<(T_LEN * H_DIM / 8 + 255) / 256, 256>>>(phd, phdb, T_LEN * H_DIM);
    transpose_b_kernel<<<dim3(H_DIM / 32, SH_LEN / 32), dim3(32, 8)>>>(phh, phhTb,
                                                                       SH_LEN, H_DIM);
    // 6. attention scores = hd @ hh^T
    gemm_tc<<<dim3(SH_LEN / 128, T_LEN / 128), 256>>>(phdb, phhb, pat, nullptr, nullptr,
                                                      T_LEN, SH_LEN, H_DIM);
    // 7. softmax rows -> bf16
    softmax_kernel<<<T_LEN, 256>>>();
    // 8. context = attn @ hh  (as attn @ (hh^T)^T)
    gemm_tc<<<dim3(H_DIM / 128, T_LEN / 128), 256>>>(patb, phhTb, pcx, nullptr, nullptr,
                                                     T_LEN, H_DIM, SH_LEN);
    // 9. concat -> bf16
    concat_kernel<<<T_LEN, 272>>>(emb_uid, uid);
    // 10. FC: y = outc @ fcW^T + fcb
    gemm_tc<<<dim3((LOC_N + 127) / 128, T_LEN / 128), 256>>>(potb, pfcb, py, fcb, nullptr,
                                                             T_LEN, LOC_N, FC_K);
    // 11. log_softmax -> output
    logsoftmax_kernel<<<T_LEN, 256>>>(out);
}

// round 4
// speedup vs baseline: 2.1017x; 1.8139x over previous
#include <cuda_runtime.h>
#include <cuda_bf16.h>
#include <math.h>
#include <stdint.h>

#define S_LEN 5120
#define T_LEN 1024
#define SH_LEN 4096
#define H_DIM 512
#define D_DIM 608
#define G_DIM 2048
#define LOC_N 50000
#define FC_K 1088
#define DU_DIM 64
#define NB 128   // LSTM blocks per group

// ---------------- scratch (device globals; no allocation allowed) ----------
__device__ float g_x[S_LEN * D_DIM];
__device__ float g_pre_enc[SH_LEN * G_DIM];
__device__ float g_pre_dec[T_LEN * G_DIM];
__device__ float g_hh[SH_LEN * H_DIM];
__device__ float g_hd[T_LEN * H_DIM];
__device__ float g_attn[(size_t)T_LEN * SH_LEN];
__device__ float g_ctx[T_LEN * H_DIM];
__device__ float g_y[(size_t)T_LEN * LOC_N];
__device__ unsigned int g_cnt_enc[SH_LEN];
__device__ unsigned int g_cnt_dec[T_LEN];

// bf16 operand buffers
__device__ __nv_bfloat16 g_xb[S_LEN * D_DIM];
__device__ __nv_bfloat16 g_wihb_e[G_DIM * D_DIM];
__device__ __nv_bfloat16 g_wihb_d[G_DIM * D_DIM];
__device__ __nv_bfloat16 g_fcWb[(size_t)LOC_N * FC_K];
__device__ __nv_bfloat16 g_hhb[SH_LEN * H_DIM];
__device__ __nv_bfloat16 g_hdb[T_LEN * H_DIM];
__device__ __nv_bfloat16 g_hhTb[H_DIM * SH_LEN];
__device__ __nv_bfloat16 g_attnb[(size_t)T_LEN * SH_LEN];
__device__ __nv_bfloat16 g_outb[T_LEN * FC_K];

// ---------------- embedding gather ----------------
__global__ void embed_kernel(const int* __restrict__ loc, const int* __restrict__ tim,
                             const int* __restrict__ clu,
                             const float* __restrict__ el, const float* __restrict__ et,
                             const float* __restrict__ ec) {
    int s = blockIdx.x, t = threadIdx.x;
    float* xrow = &g_x[(size_t)s * D_DIM];
    if (t < 128) {
        float4 v = *(const float4*)&el[(size_t)loc[s] * 512 + t * 4];
        *(float4*)&xrow[t * 4] = v;
    } else if (t < 136) {
        int j = t - 128;
        float4 v = *(const float4*)&et[(size_t)tim[s] * 32 + j * 4];
        *(float4*)&xrow[512 + j * 4] = v;
    } else if (t < 152) {
        int j = t - 136;
        float4 v = *(const float4*)&ec[(size_t)clu[s] * 64 + j * 4];
        *(float4*)&xrow[544 + j * 4] = v;
    }
}

// ---------------- fp32 -> bf16 conversion (8 elems/thread) ----------------
__global__ void f2b_kernel(const float* __restrict__ in, __nv_bfloat16* __restrict__ out,
                           int n) {
    int i = (blockIdx.x * blockDim.x + threadIdx.x) * 8;
    if (i < n) {
        float4 v0 = *(const float4*)&in[i];
        float4 v1 = *(const float4*)&in[i + 4];
        __nv_bfloat162 o[4];
        o[0] = __float22bfloat162_rn(make_float2(v0.x, v0.y));
        o[1] = __float22bfloat162_rn(make_float2(v0.z, v0.w));
        o[2] = __float22bfloat162_rn(make_float2(v1.x, v1.y));
        o[3] = __float22bfloat162_rn(make_float2(v1.z, v1.w));
        *(int4*)&out[i] = *(int4*)o;
    }
}

__global__ void cnt_reset_kernel() {
    int i = blockIdx.x * blockDim.x + threadIdx.x;
    if (i < SH_LEN) g_cnt_enc[i] = 0u;
    if (i < T_LEN) g_cnt_dec[i] = 0u;
}

// transpose fp32 [R,C] -> bf16 [C,R]
__global__ void transpose_b_kernel(const float* __restrict__ in,
                                   __nv_bfloat16* __restrict__ out, int R, int C) {
    __shared__ float tile[32][33];
    int x = blockIdx.x * 32 + threadIdx.x;
    int y = blockIdx.y * 32 + threadIdx.y;
#pragma unroll
    for (int j = 0; j < 32; j += 8)
        tile[threadIdx.y + j][threadIdx.x] = in[(size_t)(y + j) * C + x];
    __syncthreads();
    int ox = blockIdx.y * 32 + threadIdx.x;
    int oy = blockIdx.x * 32 + threadIdx.y;
#pragma unroll
    for (int j = 0; j < 32; j += 8)
        out[(size_t)(oy + j) * R + ox] = __float2bfloat16(tile[threadIdx.x][threadIdx.y + j]);
}

// ---------------- bf16 tensor-core GEMM: C = A @ B^T + bias -------------
__device__ __forceinline__ void ldsm4(uint32_t& r0, uint32_t& r1, uint32_t& r2,
                                      uint32_t& r3, uint32_t a) {
    asm volatile("ldmatrix.sync.aligned.m8n8.x4.shared.b16 {%0,%1,%2,%3}, [%4];"
                 : "=r"(r0), "=r"(r1), "=r"(r2), "=r"(r3) : "r"(a));
}
__device__ __forceinline__ void mma16816(float* c, const uint32_t* a, const uint32_t* b) {
    asm volatile(
        "mma.sync.aligned.m16n8k16.row.col.f32.bf16.bf16.f32 "
        "{%0,%1,%2,%3},{%4,%5,%6,%7},{%8,%9},{%0,%1,%2,%3};"
        : "+f"(c[0]), "+f"(c[1]), "+f"(c[2]), "+f"(c[3])
        : "r"(a[0]), "r"(a[1]), "r"(a[2]), "r"(a[3]), "r"(b[0]), "r"(b[1]));
}

__global__ void __launch_bounds__(256) gemm_tc(
    const __nv_bfloat16* __restrict__ A, const __nv_bfloat16* __restrict__ B,
    float* __restrict__ C, const float* __restrict__ bias1,
    const float* __restrict__ bias2, int M, int N, int K)
{
    __shared__ __nv_bfloat16 As[2][128][40];
    __shared__ __nv_bfloat16 Bs[2][128][40];
    const int tid = threadIdx.x, lane = tid & 31, warp = tid >> 5;
    const int wm = warp & 1, wn = warp >> 1;   // 2 x 4 warp grid
    const int m0 = blockIdx.y * 128, n0 = blockIdx.x * 128;
    const int lr = tid >> 2;          // 0..63
    const int lc = (tid & 3) << 3;    // 0,8,16,24
    const int grp = lane >> 3, lrr = lane & 7;

    float acc[4][4][4];
#pragma unroll
    for (int i = 0; i < 4; i++)
#pragma unroll
        for (int j = 0; j < 4; j++)
#pragma unroll
            for (int r = 0; r < 4; r++) acc[i][j][r] = 0.f;

    int4 ra0, ra1, rb0, rb1;
    const int KT = K >> 5;
    const int4 zero4 = make_int4(0, 0, 0, 0);

    {
        const __nv_bfloat16* Ap = A + (size_t)(m0 + lr) * K + lc;
        ra0 = *(const int4*)Ap;
        ra1 = *(const int4*)(Ap + (size_t)64 * K);
        int nr0 = n0 + lr, nr1 = nr0 + 64;
        rb0 = (nr0 < N) ? *(const int4*)(B + (size_t)nr0 * K + lc) : zero4;
        rb1 = (nr1 < N) ? *(const int4*)(B + (size_t)nr1 * K + lc) : zero4;
    }
    *(int4*)&As[0][lr][lc] = ra0;
    *(int4*)&As[0][lr + 64][lc] = ra1;
    *(int4*)&Bs[0][lr][lc] = rb0;
    *(int4*)&Bs[0][lr + 64][lc] = rb1;
    __syncthreads();

    for (int kt = 0; kt < KT; kt++) {
        const int buf = kt & 1;
        if (kt + 1 < KT) {
            const int k0 = (kt + 1) << 5;
            const __nv_bfloat16* Ap = A + (size_t)(m0 + lr) * K + k0 + lc;
            ra0 = *(const int4*)Ap;
            ra1 = *(const int4*)(Ap + (size_t)64 * K);
            int nr0 = n0 + lr, nr1 = nr0 + 64;
            rb0 = (nr0 < N) ? *(const int4*)(B + (size_t)nr0 * K + k0 + lc) : zero4;
            rb1 = (nr1 < N) ? *(const int4*)(B + (size_t)nr1 * K + k0 + lc) : zero4;
        }
#pragma unroll
        for (int kk = 0; kk < 2; kk++) {
            const int kb = kk << 4;
            uint32_t af[4][4], bf[4][2];
#pragma unroll
            for (int mt = 0; mt < 4; mt++) {
                int row = wm * 64 + mt * 16 + ((grp & 1) << 3) + lrr;
                int col = kb + ((grp >> 1) << 3);
                ldsm4(af[mt][0], af[mt][1], af[mt][2], af[mt][3],
                      (uint32_t)__cvta_generic_to_shared(&As[buf][row][col]));
            }
#pragma unroll
            for (int nt2 = 0; nt2 < 2; nt2++) {
                int row = wn * 32 + nt2 * 16 + ((grp >> 1) << 3) + lrr;
                int col = kb + ((grp & 1) << 3);
                uint32_t r0, r1, r2, r3;
                ldsm4(r0, r1, r2, r3,
                      (uint32_t)__cvta_generic_to_shared(&Bs[buf][row][col]));
                bf[nt2 * 2][0] = r0; bf[nt2 * 2][1] = r1;
                bf[nt2 * 2 + 1][0] = r2; bf[nt2 * 2 + 1][1] = r3;
            }
#pragma unroll
            for (int mt = 0; mt < 4; mt++)
#pragma unroll
                for (int nt = 0; nt < 4; nt++)
                    mma16816(acc[mt][nt], af[mt], bf[nt]);
        }
        if (kt + 1 < KT) {
            const int nb = buf ^ 1;
            *(int4*)&As[nb][lr][lc] = ra0;
            *(int4*)&As[nb][lr + 64][lc] = ra1;
            *(int4*)&Bs[nb][lr][lc] = rb0;
            *(int4*)&Bs[nb][lr + 64][lc] = rb1;
            __syncthreads();
        }
    }

#pragma unroll
    for (int nt = 0; nt < 4; nt++) {
        int col = n0 + wn * 32 + nt * 8 + ((lane & 3) << 1);
        if (col >= N) continue;
        float b0 = 0.f, b1 = 0.f;
        if (bias1) { b0 += bias1[col]; b1 += bias1[col + 1]; }
        if (bias2) { b0 += bias2[col]; b1 += bias2[col + 1]; }
#pragma unroll
        for (int mt = 0; mt < 4; mt++) {
            int row = m0 + wm * 64 + mt * 16 + (lane >> 2);
            float2 v0 = make_float2(acc[mt][nt][0] + b0, acc[mt][nt][1] + b1);
            float2 v1 = make_float2(acc[mt][nt][2] + b0, acc[mt][nt][3] + b1);
            *(float2*)&C[(size_t)row * N + col] = v0;
            *(float2*)&C[(size_t)(row + 8) * N + col] = v1;
        }
    }
}

// ---------------- fused persistent LSTM (enc + dec concurrently) ----------
__device__ __forceinline__ float tanhap(float x) {
    float y; asm("tanh.approx.f32 %0, %1;" : "=f"(y) : "f"(x)); return y;
}
__device__ __forceinline__ float sigap(float x) {
    return 0.5f * tanhap(0.5f * x) + 0.5f;
}

// blocks [0,128): encoder, T=4096.  blocks [128,256): decoder, T=1024.
__global__ void __launch_bounds__(256) lstm_fused_kernel(
    const float* __restrict__ preE, const float* __restrict__ WhhE, float* __restrict__ histE,
    const float* __restrict__ preD, const float* __restrict__ WhhD, float* __restrict__ histD)
{
    __shared__ __align__(16) float Ws[16][H_DIM];
    __shared__ __align__(16) float hs[H_DIM];
    __shared__ float gs[16];
    __shared__ float ps[16];
    __shared__ float cs[4];

    const bool enc = blockIdx.x < NB;
    const float* pre  = enc ? preE : preD;
    const float* Whh  = enc ? WhhE : WhhD;
    float* hist       = enc ? histE : histD;
    unsigned int* cnt = enc ? g_cnt_enc : g_cnt_dec;
    const int T       = enc ? SH_LEN : T_LEN;

    const int b = blockIdx.x & (NB - 1);
    const int tid = threadIdx.x;
    const int lane = tid & 31;
    const int warp = tid >> 5;
    const int r0 = warp * 2, r1 = r0 + 1;

    // load Whh slice (16 gate rows of this block)
    for (int r = 0; r < 16; r++) {
        int grow = (r >> 2) * H_DIM + b * 4 + (r & 3);
        for (int k = tid; k < H_DIM; k += 256)
            Ws[r][k] = Whh[(size_t)grow * H_DIM + k];
    }
    if (tid < 4) cs[tid] = 0.f;

    const float4* Ws4_0 = (const float4*)&Ws[r0][0];
    const float4* Ws4_1 = (const float4*)&Ws[r1][0];
    const float4* hs4 = (const float4*)hs;

    for (int t = 0; t < T; t++) {
        // prefetch per-step gate bias (overlaps the h broadcast)
        float psv = 0.f;
        if (tid < 16)
            psv = __ldg(&pre[(size_t)t * G_DIM + (tid >> 2) * H_DIM + b * 4 + (tid & 3)]);

        if (t == 0) {
            hs[2 * tid] = 0.f; hs[2 * tid + 1] = 0.f;
        } else {
            float2 hv = __ldcg((const float2*)&hist[(size_t)(t - 1) * H_DIM + 2 * tid]);
            hs[2 * tid] = hv.x; hs[2 * tid + 1] = hv.y;
        }
        if (tid < 16) ps[tid] = psv;
        __syncthreads();

        // dot: lane handles 16 consecutive h elems (conflict-free float4 LDS)
        float a0 = 0.f, a1 = 0.f;
#pragma unroll
        for (int jj = 0; jj < 4; jj++) {
            int idx = jj * 32 + lane;
            float4 h4 = hs4[idx];
            float4 w0 = Ws4_0[idx];
            float4 w1 = Ws4_1[idx];
            a0 += h4.x * w0.x + h4.y * w0.y + h4.z * w0.z + h4.w * w0.w;
            a1 += h4.x * w1.x + h4.y * w1.y + h4.z * w1.z + h4.w * w1.w;
        }
#pragma unroll
        for (int o = 16; o > 0; o >>= 1) {
            a0 += __shfl_down_sync(0xffffffffu, a0, o);
            a1 += __shfl_down_sync(0xffffffffu, a1, o);
        }
        if (lane == 0) { gs[r0] = a0 + ps[r0]; gs[r1] = a1 + ps[r1]; }
        __syncthreads();

        if (tid < 4) {
            float ig = sigap(gs[tid]);
            float fg = sigap(gs[4 + tid]);
            float gg = tanhap(gs[8 + tid]);
            float og = sigap(gs[12 + tid]);
            float c = fg * cs[tid] + ig * gg;
            cs[tid] = c;
            float h = og * tanhap(c);
            __stcg(&hist[(size_t)t * H_DIM + b * 4 + tid], h);
        }
        __syncthreads();

        // light grid barrier: release-arrive + acquire-poll on per-step counter
        if (tid == 0) {
            __threadfence();
            unsigned int* cp = cnt + t;
            asm volatile("red.relaxed.gpu.global.add.u32 [%0], 1;" :: "l"(cp) : "memory");
            unsigned int v;
            do {
                asm volatile("ld.acquire.gpu.global.u32 %0, [%1];"
                             : "=r"(v) : "l"(cp) : "memory");
            } while (v < NB);
        }
        __syncthreads();
    }
}

// ---------------- reductions ----------------
__device__ __forceinline__ float block_max_256(float v, float* red) {
#pragma unroll
    for (int o = 16; o > 0; o >>= 1) v = fmaxf(v, __shfl_xor_sync(0xffffffffu, v, o));
    if ((threadIdx.x & 31) == 0) red[threadIdx.x >> 5] = v;
    __syncthreads();
    if (threadIdx.x < 32) {
        float x = (threadIdx.x < 8) ? red[threadIdx.x] : -1e30f;
#pragma unroll
        for (int o = 4; o > 0; o >>= 1) x = fmaxf(x, __shfl_xor_sync(0xffffffffu, x, o));
        if (threadIdx.x == 0) red[0] = x;
    }
    __syncthreads();
    float r = red[0];
    __syncthreads();
    return r;
}

__device__ __forceinline__ float block_sum_256(float v, float* red) {
#pragma unroll
    for (int o = 16; o > 0; o >>= 1) v += __shfl_xor_sync(0xffffffffu, v, o);
    if ((threadIdx.x & 31) == 0) red[threadIdx.x >> 5] = v;
    __syncthreads();
    if (threadIdx.x < 32) {
        float x = (threadIdx.x < 8) ? red[threadIdx.x] : 0.f;
#pragma unroll
        for (int o = 4; o > 0; o >>= 1) x += __shfl_xor_sync(0xffffffffu, x, o);
        if (threadIdx.x == 0) red[0] = x;
    }
    __syncthreads();
    float r = red[0];
    __syncthreads();
    return r;
}

// softmax over rows of g_attn [T_LEN, SH_LEN] -> bf16 g_attnb
__global__ void __launch_bounds__(256) softmax_kernel() {
    __shared__ float red[8];
    const int row = blockIdx.x, tid = threadIdx.x;
    const float* X = &g_attn[(size_t)row * SH_LEN];
    __nv_bfloat16* O = &g_attnb[(size_t)row * SH_LEN];
    float v[16];
    float m = -1e30f;
#pragma unroll
    for (int j = 0; j < 16; j++) { v[j] = X[tid + j * 256]; m = fmaxf(m, v[j]); }
    m = block_max_256(m, red);
    float s = 0.f;
#pragma unroll
    for (int j = 0; j < 16; j++) { v[j] = expf(v[j] - m); s += v[j]; }
    s = block_sum_256(s, red);
    float inv = 1.f / s;
#pragma unroll
    for (int j = 0; j < 16; j++) O[tid + j * 256] = __float2bfloat16(v[j] * inv);
}

// log_softmax over rows of g_y [T_LEN, LOC_N] -> out
__global__ void __launch_bounds__(256) logsoftmax_kernel(float* __restrict__ out) {
    __shared__ float red[8];
    const int row = blockIdx.x, tid = threadIdx.x;
    const float* Y = &g_y[(size_t)row * LOC_N];
    float* O = &out[(size_t)row * LOC_N];
    float m = -1e30f;
    for (int c = tid; c < LOC_N; c += 256) m = fmaxf(m, Y[c]);
    m = block_max_256(m, red);
    float s = 0.f;
    for (int c = tid; c < LOC_N; c += 256) s += expf(Y[c] - m);
    s = block_sum_256(s, red);
    float ls = m + logf(s);
    for (int c = tid; c < LOC_N; c += 256) O[c] = Y[c] - ls;
}

// concat [hd | ctx | uid_emb] -> g_outb bf16 [T_LEN, FC_K]
__global__ void concat_kernel(const float* __restrict__ emb_uid, const int* __restrict__ uid) {
    int row = blockIdx.x, t = threadIdx.x;
    float4 v;
    if (t < 128)       v = *(const float4*)&g_hd[(size_t)row * H_DIM + t * 4];
    else if (t < 256)  v = *(const float4*)&g_ctx[(size_t)row * H_DIM + (t - 128) * 4];
    else               v = *(const float4*)&emb_uid[(size_t)uid[0] * DU_DIM + (t - 256) * 4];
    __nv_bfloat162 o[2];
    o[0] = __float22bfloat162_rn(make_float2(v.x, v.y));
    o[1] = __float22bfloat162_rn(make_float2(v.z, v.w));
    *(uint2*)&g_outb[(size_t)row * FC_K + t * 4] = *(uint2*)o;
}

// ---------------- host ----------------
extern "C" void kernel_launch(void* const* d_in, const int* in_sizes, int n_in,
                              void* d_out, int out_size) {
    const int* loc = (const int*)d_in[0];
    const int* tim = (const int*)d_in[1];
    const int* clu = (const int*)d_in[2];
    const int* uid = (const int*)d_in[3];
    const float* emb_loc = (const float*)d_in[5];
    const float* emb_tim = (const float*)d_in[6];
    const float* emb_clu = (const float*)d_in[7];
    const float* emb_uid = (const float*)d_in[8];
    const float* eWih = (const float*)d_in[9];
    const float* eWhh = (const float*)d_in[10];
    const float* ebih = (const float*)d_in[11];
    const float* ebhh = (const float*)d_in[12];
    const float* dWih = (const float*)d_in[13];
    const float* dWhh = (const float*)d_in[14];
    const float* dbih = (const float*)d_in[15];
    const float* dbhh = (const float*)d_in[16];
    const float* fcW = (const float*)d_in[17];
    const float* fcb = (const float*)d_in[18];
    float* out = (float*)d_out;

    float *px, *ppe, *ppd, *phh, *phd, *pat, *pcx, *py;
    cudaGetSymbolAddress((void**)&px,  g_x);
    cudaGetSymbolAddress((void**)&ppe, g_pre_enc);
    cudaGetSymbolAddress((void**)&ppd, g_pre_dec);
    cudaGetSymbolAddress((void**)&phh, g_hh);
    cudaGetSymbolAddress((void**)&phd, g_hd);
    cudaGetSymbolAddress((void**)&pat, g_attn);
    cudaGetSymbolAddress((void**)&pcx, g_ctx);
    cudaGetSymbolAddress((void**)&py,  g_y);
    __nv_bfloat16 *pxb, *pweb, *pwdb, *pfcb, *phhb, *phdb, *phhTb, *patb, *potb;
    cudaGetSymbolAddress((void**)&pxb,   g_xb);
    cudaGetSymbolAddress((void**)&pweb,  g_wihb_e);
    cudaGetSymbolAddress((void**)&pwdb,  g_wihb_d);
    cudaGetSymbolAddress((void**)&pfcb,  g_fcWb);
    cudaGetSymbolAddress((void**)&phhb,  g_hhb);
    cudaGetSymbolAddress((void**)&phdb,  g_hdb);
    cudaGetSymbolAddress((void**)&phhTb, g_hhTb);
    cudaGetSymbolAddress((void**)&patb,  g_attnb);
    cudaGetSymbolAddress((void**)&potb,  g_outb);

    // 1. embed + conversions + counter reset
    embed_kernel<<<S_LEN, 152>>>(loc, tim, clu, emb_loc, emb_tim, emb_clu);
    cnt_reset_kernel<<<(SH_LEN + 255) / 256, 256>>>();
    f2b_kernel<<<(S_LEN * D_DIM / 8 + 255) / 256, 256>>>(px, pxb, S_LEN * D_DIM);
    f2b_kernel<<<(G_DIM * D_DIM / 8 + 255) / 256, 256>>>(eWih, pweb, G_DIM * D_DIM);
    f2b_kernel<<<(G_DIM * D_DIM / 8 + 255) / 256, 256>>>(dWih, pwdb, G_DIM * D_DIM);
    f2b_kernel<<<(LOC_N * FC_K / 8 + 255) / 256, 256>>>(fcW, pfcb, LOC_N * FC_K);

    // 2. input projections (bf16 TC), both biases folded in
    gemm_tc<<<dim3(G_DIM / 128, SH_LEN / 128), 256>>>(pxb, pweb, ppe, ebih, ebhh,
                                                      SH_LEN, G_DIM, D_DIM);
    gemm_tc<<<dim3(G_DIM / 128, T_LEN / 128), 256>>>(pxb + (size_t)SH_LEN * D_DIM, pwdb,
                                                     ppd, dbih, dbhh, T_LEN, G_DIM, D_DIM);
    // 3. both LSTMs concurrently (persistent, per-step counter barriers)
    lstm_fused_kernel<<<2 * NB, 256>>>(ppe, eWhh, phh, ppd, dWhh, phd);

    // 4. convert hidden states to bf16 (+transposed copy of hh)
    f2b_kernel<<<(SH_LEN * H_DIM / 8 + 255) / 256, 256>>>(phh, phhb, SH_LEN * H_DIM);
    f2b_kernel<<<(T_LEN * H_DIM / 8 + 255) / 256, 256>>>(phd, phdb, T_LEN * H_DIM);
    transpose_b_kernel<<<dim3(H_DIM / 32, SH_LEN / 32), dim3(32, 8)>>>(phh, phhTb,
                                                                       SH_LEN, H_DIM);
    // 5. attention scores = hd @ hh^T
    gemm_tc<<<dim3(SH_LEN / 128, T_LEN / 128), 256>>>(phdb, phhb, pat, nullptr, nullptr,
                                                      T_LEN, SH_LEN, H_DIM);
    // 6. softmax rows -> bf16
    softmax_kernel<<<T_LEN, 256>>>();
    // 7. context = attn @ hh  (as attn @ (hh^T)^T)
    gemm_tc<<<dim3(H_DIM / 128, T_LEN / 128), 256>>>(patb, phhTb, pcx, nullptr, nullptr,
                                                     T_LEN, H_DIM, SH_LEN);
    // 8. concat -> bf16
    concat_kernel<<<T_LEN, 272>>>(emb_uid, uid);
    // 9. FC: y = outc @ fcW^T + fcb
    gemm_tc<<<dim3((LOC_N + 127) / 128, T_LEN / 128), 256>>>(potb, pfcb, py, fcb, nullptr,
                                                             T_LEN, LOC_N, FC_K);
    // 10. log_softmax -> output
    logsoftmax_kernel<<<T_LEN, 256>>>(out);
}

// round 5
// speedup vs baseline: 2.1665x; 1.0308x over previous
#include <cuda_runtime.h>
#include <cuda_bf16.h>
#include <math.h>
#include <stdint.h>

#define S_LEN 5120
#define T_LEN 1024
#define SH_LEN 4096
#define H_DIM 512
#define D_DIM 608
#define G_DIM 2048
#define LOC_N 50000
#define FC_K 1088
#define DU_DIM 64
#define NB 64   // LSTM blocks per group (8 hidden units each)

// ---------------- scratch (device globals; no allocation allowed) ----------
__device__ float g_x[S_LEN * D_DIM];
__device__ float g_pre_enc[SH_LEN * G_DIM];
__device__ float g_pre_dec[T_LEN * G_DIM];
__device__ float g_hh[SH_LEN * H_DIM];
__device__ float g_hd[T_LEN * H_DIM];
__device__ float g_attn[(size_t)T_LEN * SH_LEN];
__device__ float g_ctx[T_LEN * H_DIM];
__device__ float g_y[(size_t)T_LEN * LOC_N];
__device__ unsigned int g_cnt_enc[SH_LEN];
__device__ unsigned int g_cnt_dec[T_LEN];

// bf16 operand buffers
__device__ __nv_bfloat16 g_xb[S_LEN * D_DIM];
__device__ __nv_bfloat16 g_wihb_e[G_DIM * D_DIM];
__device__ __nv_bfloat16 g_wihb_d[G_DIM * D_DIM];
__device__ __nv_bfloat16 g_fcWb[(size_t)LOC_N * FC_K];
__device__ __nv_bfloat16 g_hhb[SH_LEN * H_DIM];
__device__ __nv_bfloat16 g_hdb[T_LEN * H_DIM];
__device__ __nv_bfloat16 g_hhTb[H_DIM * SH_LEN];
__device__ __nv_bfloat16 g_attnb[(size_t)T_LEN * SH_LEN];
__device__ __nv_bfloat16 g_outb[T_LEN * FC_K];

// ---------------- embedding gather (+ LSTM counter reset fused) -----------
__global__ void embed_kernel(const int* __restrict__ loc, const int* __restrict__ tim,
                             const int* __restrict__ clu,
                             const float* __restrict__ el, const float* __restrict__ et,
                             const float* __restrict__ ec) {
    int s = blockIdx.x, t = threadIdx.x;
    if (t == 0) {
        if (s < SH_LEN) g_cnt_enc[s] = 0u;
        if (s < T_LEN) g_cnt_dec[s] = 0u;
    }
    float* xrow = &g_x[(size_t)s * D_DIM];
    if (t < 128) {
        float4 v = *(const float4*)&el[(size_t)loc[s] * 512 + t * 4];
        *(float4*)&xrow[t * 4] = v;
    } else if (t < 136) {
        int j = t - 128;
        float4 v = *(const float4*)&et[(size_t)tim[s] * 32 + j * 4];
        *(float4*)&xrow[512 + j * 4] = v;
    } else if (t < 152) {
        int j = t - 136;
        float4 v = *(const float4*)&ec[(size_t)clu[s] * 64 + j * 4];
        *(float4*)&xrow[544 + j * 4] = v;
    }
}

// ---------------- fp32 -> bf16 conversion (8 elems/thread) ----------------
__global__ void f2b_kernel(const float* __restrict__ in, __nv_bfloat16* __restrict__ out,
                           int n) {
    int i = (blockIdx.x * blockDim.x + threadIdx.x) * 8;
    if (i < n) {
        float4 v0 = *(const float4*)&in[i];
        float4 v1 = *(const float4*)&in[i + 4];
        __nv_bfloat162 o[4];
        o[0] = __float22bfloat162_rn(make_float2(v0.x, v0.y));
        o[1] = __float22bfloat162_rn(make_float2(v0.z, v0.w));
        o[2] = __float22bfloat162_rn(make_float2(v1.x, v1.y));
        o[3] = __float22bfloat162_rn(make_float2(v1.z, v1.w));
        *(int4*)&out[i] = *(int4*)o;
    }
}

// convert both Wih matrices in one launch (each is 608 blocks' worth)
__global__ void f2bw_kernel(const float* __restrict__ e, const float* __restrict__ d) {
    int bid = blockIdx.x;
    const float* in;
    __nv_bfloat16* out;
    if (bid < 608) { in = e; out = g_wihb_e; }
    else { in = d; out = g_wihb_d; bid -= 608; }
    int i = (bid * 256 + threadIdx.x) * 8;
    float4 v0 = *(const float4*)&in[i];
    float4 v1 = *(const float4*)&in[i + 4];
    __nv_bfloat162 o[4];
    o[0] = __float22bfloat162_rn(make_float2(v0.x, v0.y));
    o[1] = __float22bfloat162_rn(make_float2(v0.z, v0.w));
    o[2] = __float22bfloat162_rn(make_float2(v1.x, v1.y));
    o[3] = __float22bfloat162_rn(make_float2(v1.z, v1.w));
    *(int4*)&out[i] = *(int4*)o;
}

// ---------------- bf16 tensor-core GEMM: C = A @ B^T + bias -------------
__device__ __forceinline__ void ldsm4(uint32_t& r0, uint32_t& r1, uint32_t& r2,
                                      uint32_t& r3, uint32_t a) {
    asm volatile("ldmatrix.sync.aligned.m8n8.x4.shared.b16 {%0,%1,%2,%3}, [%4];"
                 : "=r"(r0), "=r"(r1), "=r"(r2), "=r"(r3) : "r"(a));
}
__device__ __forceinline__ void mma16816(float* c, const uint32_t* a, const uint32_t* b) {
    asm volatile(
        "mma.sync.aligned.m16n8k16.row.col.f32.bf16.bf16.f32 "
        "{%0,%1,%2,%3},{%4,%5,%6,%7},{%8,%9},{%0,%1,%2,%3};"
        : "+f"(c[0]), "+f"(c[1]), "+f"(c[2]), "+f"(c[3])
        : "r"(a[0]), "r"(a[1]), "r"(a[2]), "r"(a[3]), "r"(b[0]), "r"(b[1]));
}

__global__ void __launch_bounds__(256) gemm_tc(
    const __nv_bfloat16* __restrict__ A, const __nv_bfloat16* __restrict__ B,
    float* __restrict__ C, const float* __restrict__ bias1,
    const float* __restrict__ bias2, int M, int N, int K)
{
    __shared__ __nv_bfloat16 As[2][128][40];
    __shared__ __nv_bfloat16 Bs[2][128][40];
    const int tid = threadIdx.x, lane = tid & 31, warp = tid >> 5;
    const int wm = warp & 1, wn = warp >> 1;   // 2 x 4 warp grid
    const int m0 = blockIdx.y * 128, n0 = blockIdx.x * 128;
    const int lr = tid >> 2;          // 0..63
    const int lc = (tid & 3) << 3;    // 0,8,16,24
    const int grp = lane >> 3, lrr = lane & 7;

    float acc[4][4][4];
#pragma unroll
    for (int i = 0; i < 4; i++)
#pragma unroll
        for (int j = 0; j < 4; j++)
#pragma unroll
            for (int r = 0; r < 4; r++) acc[i][j][r] = 0.f;

    int4 ra0, ra1, rb0, rb1;
    const int KT = K >> 5;
    const int4 zero4 = make_int4(0, 0, 0, 0);

    {
        const __nv_bfloat16* Ap = A + (size_t)(m0 + lr) * K + lc;
        ra0 = *(const int4*)Ap;
        ra1 = *(const int4*)(Ap + (size_t)64 * K);
        int nr0 = n0 + lr, nr1 = nr0 + 64;
        rb0 = (nr0 < N) ? *(const int4*)(B + (size_t)nr0 * K + lc) : zero4;
        rb1 = (nr1 < N) ? *(const int4*)(B + (size_t)nr1 * K + lc) : zero4;
    }
    *(int4*)&As[0][lr][lc] = ra0;
    *(int4*)&As[0][lr + 64][lc] = ra1;
    *(int4*)&Bs[0][lr][lc] = rb0;
    *(int4*)&Bs[0][lr + 64][lc] = rb1;
    __syncthreads();

    for (int kt = 0; kt < KT; kt++) {
        const int buf = kt & 1;
        if (kt + 1 < KT) {
            const int k0 = (kt + 1) << 5;
            const __nv_bfloat16* Ap = A + (size_t)(m0 + lr) * K + k0 + lc;
            ra0 = *(const int4*)Ap;
            ra1 = *(const int4*)(Ap + (size_t)64 * K);
            int nr0 = n0 + lr, nr1 = nr0 + 64;
            rb0 = (nr0 < N) ? *(const int4*)(B + (size_t)nr0 * K + k0 + lc) : zero4;
            rb1 = (nr1 < N) ? *(const int4*)(B + (size_t)nr1 * K + k0 + lc) : zero4;
        }
#pragma unroll
        for (int kk = 0; kk < 2; kk++) {
            const int kb = kk << 4;
            uint32_t af[4][4], bf[4][2];
#pragma unroll
            for (int mt = 0; mt < 4; mt++) {
                int row = wm * 64 + mt * 16 + ((grp & 1) << 3) + lrr;
                int col = kb + ((grp >> 1) << 3);
                ldsm4(af[mt][0], af[mt][1], af[mt][2], af[mt][3],
                      (uint32_t)__cvta_generic_to_shared(&As[buf][row][col]));
            }
#pragma unroll
            for (int nt2 = 0; nt2 < 2; nt2++) {
                int row = wn * 32 + nt2 * 16 + ((grp >> 1) << 3) + lrr;
                int col = kb + ((grp & 1) << 3);
                uint32_t r0, r1, r2, r3;
                ldsm4(r0, r1, r2, r3,
                      (uint32_t)__cvta_generic_to_shared(&Bs[buf][row][col]));
                bf[nt2 * 2][0] = r0; bf[nt2 * 2][1] = r1;
                bf[nt2 * 2 + 1][0] = r2; bf[nt2 * 2 + 1][1] = r3;
            }
#pragma unroll
            for (int mt = 0; mt < 4; mt++)
#pragma unroll
                for (int nt = 0; nt < 4; nt++)
                    mma16816(acc[mt][nt], af[mt], bf[nt]);
        }
        if (kt + 1 < KT) {
            const int nb = buf ^ 1;
            *(int4*)&As[nb][lr][lc] = ra0;
            *(int4*)&As[nb][lr + 64][lc] = ra1;
            *(int4*)&Bs[nb][lr][lc] = rb0;
            *(int4*)&Bs[nb][lr + 64][lc] = rb1;
            __syncthreads();
        }
    }

#pragma unroll
    for (int nt = 0; nt < 4; nt++) {
        int col = n0 + wn * 32 + nt * 8 + ((lane & 3) << 1);
        if (col >= N) continue;
        float b0 = 0.f, b1 = 0.f;
        if (bias1) { b0 += bias1[col]; b1 += bias1[col + 1]; }
        if (bias2) { b0 += bias2[col]; b1 += bias2[col + 1]; }
#pragma unroll
        for (int mt = 0; mt < 4; mt++) {
            int row = m0 + wm * 64 + mt * 16 + (lane >> 2);
            float2 v0 = make_float2(acc[mt][nt][0] + b0, acc[mt][nt][1] + b1);
            float2 v1 = make_float2(acc[mt][nt][2] + b0, acc[mt][nt][3] + b1);
            *(float2*)&C[(size_t)row * N + col] = v0;
            *(float2*)&C[(size_t)(row + 8) * N + col] = v1;
        }
    }
}

// ---------------- fused persistent LSTM (enc + dec concurrently) ----------
__device__ __forceinline__ float tanhap(float x) {
    float y; asm("tanh.approx.f32 %0, %1;" : "=f"(y) : "f"(x)); return y;
}
__device__ __forceinline__ float sigap(float x) {
    return 0.5f * tanhap(0.5f * x) + 0.5f;
}

// blocks [0,64): encoder T=4096.  blocks [64,128): decoder T=1024.
// Block b owns hidden units [8b, 8b+8) = 32 gate rows; local row r: gate=r>>3, unit=r&7.
// Warp w computes rows 4w..4w+3; lane caches its 16-float K-chunk of each row in regs.
__global__ void __launch_bounds__(256) lstm_fused_kernel(
    const float* __restrict__ preE, const float* __restrict__ WhhE, float* __restrict__ histE,
    const float* __restrict__ preD, const float* __restrict__ WhhD, float* __restrict__ histD)
{
    __shared__ __align__(16) float hs[H_DIM];
    __shared__ float gs[32];
    __shared__ float ps[32];
    __shared__ float cs[8];

    const bool enc = blockIdx.x < NB;
    const float* pre  = enc ? preE : preD;
    const float* Whh  = enc ? WhhE : WhhD;
    float* hist       = enc ? histE : histD;
    __nv_bfloat16* hb = enc ? g_hhb : g_hdb;
    unsigned int* cnt = enc ? g_cnt_enc : g_cnt_dec;
    const int T       = enc ? SH_LEN : T_LEN;

    const int b = enc ? blockIdx.x : blockIdx.x - NB;
    const int tid = threadIdx.x, lane = tid & 31, warp = tid >> 5;

    // cache Whh rows in registers (loop-invariant)
    float w[4][16];
#pragma unroll
    for (int rr = 0; rr < 4; rr++) {
        int r = warp * 4 + rr, g = r >> 3, u = r & 7;
        int grow = g * H_DIM + b * 8 + u;
        const float4* src = (const float4*)&Whh[(size_t)grow * H_DIM + lane * 16];
#pragma unroll
        for (int j = 0; j < 4; j++) {
            float4 v = src[j];
            w[rr][4 * j] = v.x; w[rr][4 * j + 1] = v.y;
            w[rr][4 * j + 2] = v.z; w[rr][4 * j + 3] = v.w;
        }
    }
    if (tid < 8) cs[tid] = 0.f;

    float psv = 0.f;
    if (tid < 32)
        psv = __ldg(&pre[(tid >> 3) * H_DIM + b * 8 + (tid & 7)]);

    for (int t = 0; t < T; t++) {
        if (t == 0) {
            hs[2 * tid] = 0.f; hs[2 * tid + 1] = 0.f;
        } else {
            float2 hv = __ldcg((const float2*)&hist[(size_t)(t - 1) * H_DIM + 2 * tid]);
            hs[2 * tid] = hv.x; hs[2 * tid + 1] = hv.y;
        }
        if (tid < 32) ps[tid] = psv;
        __syncthreads();

        // prefetch next step's gate bias (long latency, fully off critical path)
        if (tid < 32 && t + 1 < T)
            psv = __ldg(&pre[(size_t)(t + 1) * G_DIM + (tid >> 3) * H_DIM + b * 8 + (tid & 7)]);

        // dot: h chunk (4 float4 from smem, reused across 4 rows) x reg weights
        float acc[4] = {0.f, 0.f, 0.f, 0.f};
        const float4* h4p = (const float4*)&hs[lane * 16];
#pragma unroll
        for (int j = 0; j < 4; j++) {
            float4 h4 = h4p[j];
#pragma unroll
            for (int rr = 0; rr < 4; rr++)
                acc[rr] += w[rr][4 * j] * h4.x + w[rr][4 * j + 1] * h4.y
                         + w[rr][4 * j + 2] * h4.z + w[rr][4 * j + 3] * h4.w;
        }
#pragma unroll
        for (int o = 16; o > 0; o >>= 1) {
#pragma unroll
            for (int rr = 0; rr < 4; rr++)
                acc[rr] += __shfl_xor_sync(0xffffffffu, acc[rr], o);
        }
        if (lane == 0) {
#pragma unroll
            for (int rr = 0; rr < 4; rr++)
                gs[warp * 4 + rr] = acc[rr] + ps[warp * 4 + rr];
        }
        __syncthreads();

        if (tid < 8) {
            float ig = sigap(gs[tid]);
            float fg = sigap(gs[8 + tid]);
            float gg = tanhap(gs[16 + tid]);
            float og = sigap(gs[24 + tid]);
            float c = fg * cs[tid] + ig * gg;
            cs[tid] = c;
            float h = og * tanhap(c);
            int gu = b * 8 + tid;
            __stcg(&hist[(size_t)t * H_DIM + gu], h);
            hb[(size_t)t * H_DIM + gu] = __float2bfloat16(h);
            if (enc) g_hhTb[(size_t)gu * SH_LEN + t] = __float2bfloat16(h);
        }
        __syncthreads();

        // release-arrive + acquire-poll on per-step counter
        if (tid == 0) {
            unsigned int* cp = cnt + t;
            asm volatile("red.release.gpu.global.add.u32 [%0], 1;" :: "l"(cp) : "memory");
            unsigned int v;
            do {
                asm volatile("ld.acquire.gpu.global.u32 %0, [%1];"
                             : "=r"(v) : "l"(cp) : "memory");
            } while (v < NB);
        }
        __syncthreads();
    }
}

// ---------------- reductions ----------------
__device__ __forceinline__ float block_max_256(float v, float* red) {
#pragma unroll
    for (int o = 16; o > 0; o >>= 1) v = fmaxf(v, __shfl_xor_sync(0xffffffffu, v, o));
    if ((threadIdx.x & 31) == 0) red[threadIdx.x >> 5] = v;
    __syncthreads();
    if (threadIdx.x < 32) {
        float x = (threadIdx.x < 8) ? red[threadIdx.x] : -1e30f;
#pragma unroll
        for (int o = 4; o > 0; o >>= 1) x = fmaxf(x, __shfl_xor_sync(0xffffffffu, x, o));
        if (threadIdx.x == 0) red[0] = x;
    }
    __syncthreads();
    float r = red[0];
    __syncthreads();
    return r;
}

__device__ __forceinline__ float block_sum_256(float v, float* red) {
#pragma unroll
    for (int o = 16; o > 0; o >>= 1) v += __shfl_xor_sync(0xffffffffu, v, o);
    if ((threadIdx.x & 31) == 0) red[threadIdx.x >> 5] = v;
    __syncthreads();
    if (threadIdx.x < 32) {
        float x = (threadIdx.x < 8) ? red[threadIdx.x] : 0.f;
#pragma unroll
        for (int o = 4; o > 0; o >>= 1) x += __shfl_xor_sync(0xffffffffu, x, o);
        if (threadIdx.x == 0) red[0] = x;
    }
    __syncthreads();
    float r = red[0];
    __syncthreads();
    return r;
}

// softmax over rows of g_attn [T_LEN, SH_LEN] -> bf16 g_attnb
__global__ void __launch_bounds__(256) softmax_kernel() {
    __shared__ float red[8];
    const int row = blockIdx.x, tid = threadIdx.x;
    const float* X = &g_attn[(size_t)row * SH_LEN];
    __nv_bfloat16* O = &g_attnb[(size_t)row * SH_LEN];
    float v[16];
    float m = -1e30f;
#pragma unroll
    for (int j = 0; j < 16; j++) { v[j] = X[tid + j * 256]; m = fmaxf(m, v[j]); }
    m = block_max_256(m, red);
    float s = 0.f;
#pragma unroll
    for (int j = 0; j < 16; j++) { v[j] = expf(v[j] - m); s += v[j]; }
    s = block_sum_256(s, red);
    float inv = 1.f / s;
#pragma unroll
    for (int j = 0; j < 16; j++) O[tid + j * 256] = __float2bfloat16(v[j] * inv);
}

// log_softmax over rows of g_y [T_LEN, LOC_N] -> out
__global__ void __launch_bounds__(256) logsoftmax_kernel(float* __restrict__ out) {
    __shared__ float red[8];
    const int row = blockIdx.x, tid = threadIdx.x;
    const float* Y = &g_y[(size_t)row * LOC_N];
    float* O = &out[(size_t)row * LOC_N];
    float m = -1e30f;
    for (int c = tid; c < LOC_N; c += 256) m = fmaxf(m, Y[c]);
    m = block_max_256(m, red);
    float s = 0.f;
    for (int c = tid; c < LOC_N; c += 256) s += expf(Y[c] - m);
    s = block_sum_256(s, red);
    float ls = m + logf(s);
    for (int c = tid; c < LOC_N; c += 256) O[c] = Y[c] - ls;
}

// concat [hd | ctx | uid_emb] -> g_outb bf16 [T_LEN, FC_K]
__global__ void concat_kernel(const float* __restrict__ emb_uid, const int* __restrict__ uid) {
    int row = blockIdx.x, t = threadIdx.x;
    float4 v;
    if (t < 128)       v = *(const float4*)&g_hd[(size_t)row * H_DIM + t * 4];
    else if (t < 256)  v = *(const float4*)&g_ctx[(size_t)row * H_DIM + (t - 128) * 4];
    else               v = *(const float4*)&emb_uid[(size_t)uid[0] * DU_DIM + (t - 256) * 4];
    __nv_bfloat162 o[2];
    o[0] = __float22bfloat162_rn(make_float2(v.x, v.y));
    o[1] = __float22bfloat162_rn(make_float2(v.z, v.w));
    *(uint2*)&g_outb[(size_t)row * FC_K + t * 4] = *(uint2*)o;
}

// ---------------- host ----------------
extern "C" void kernel_launch(void* const* d_in, const int* in_sizes, int n_in,
                              void* d_out, int out_size) {
    const int* loc = (const int*)d_in[0];
    const int* tim = (const int*)d_in[1];
    const int* clu = (const int*)d_in[2];
    const int* uid = (const int*)d_in[3];
    const float* emb_loc = (const float*)d_in[5];
    const float* emb_tim = (const float*)d_in[6];
    const float* emb_clu = (const float*)d_in[7];
    const float* emb_uid = (const float*)d_in[8];
    const float* eWih = (const float*)d_in[9];
    const float* eWhh = (const float*)d_in[10];
    const float* ebih = (const float*)d_in[11];
    const float* ebhh = (const float*)d_in[12];
    const float* dWih = (const float*)d_in[13];
    const float* dWhh = (const float*)d_in[14];
    const float* dbih = (const float*)d_in[15];
    const float* dbhh = (const float*)d_in[16];
    const float* fcW = (const float*)d_in[17];
    const float* fcb = (const float*)d_in[18];
    float* out = (float*)d_out;

    float *px, *ppe, *ppd, *phh, *phd, *pat, *pcx, *py;
    cudaGetSymbolAddress((void**)&px,  g_x);
    cudaGetSymbolAddress((void**)&ppe, g_pre_enc);
    cudaGetSymbolAddress((void**)&ppd, g_pre_dec);
    cudaGetSymbolAddress((void**)&phh, g_hh);
    cudaGetSymbolAddress((void**)&phd, g_hd);
    cudaGetSymbolAddress((void**)&pat, g_attn);
    cudaGetSymbolAddress((void**)&pcx, g_ctx);
    cudaGetSymbolAddress((void**)&py,  g_y);
    __nv_bfloat16 *pxb, *pweb, *pwdb, *pfcb, *phhb, *phdb, *phhTb, *patb, *potb;
    cudaGetSymbolAddress((void**)&pxb,   g_xb);
    cudaGetSymbolAddress((void**)&pweb,  g_wihb_e);
    cudaGetSymbolAddress((void**)&pwdb,  g_wihb_d);
    cudaGetSymbolAddress((void**)&pfcb,  g_fcWb);
    cudaGetSymbolAddress((void**)&phhb,  g_hhb);
    cudaGetSymbolAddress((void**)&phdb,  g_hdb);
    cudaGetSymbolAddress((void**)&phhTb, g_hhTb);
    cudaGetSymbolAddress((void**)&patb,  g_attnb);
    cudaGetSymbolAddress((void**)&potb,  g_outb);

    // launch order arranged so the LSTM is launch #6 (ncu -s 5 -c 1)
    // 1. embed (+ counter reset)
    embed_kernel<<<S_LEN, 152>>>(loc, tim, clu, emb_loc, emb_tim, emb_clu);
    // 2-3. conversions needed before LSTM
    f2b_kernel<<<(S_LEN * D_DIM / 8 + 255) / 256, 256>>>(px, pxb, S_LEN * D_DIM);
    f2bw_kernel<<<1216, 256>>>(eWih, dWih);
    // 4-5. input projections (bf16 TC), both biases folded in
    gemm_tc<<<dim3(G_DIM / 128, SH_LEN / 128), 256>>>(pxb, pweb, ppe, ebih, ebhh,
                                                      SH_LEN, G_DIM, D_DIM);
    gemm_tc<<<dim3(G_DIM / 128, T_LEN / 128), 256>>>(pxb + (size_t)SH_LEN * D_DIM, pwdb,
                                                     ppd, dbih, dbhh, T_LEN, G_DIM, D_DIM);
    // 6. both LSTMs concurrently (emits fp32 + bf16 + transposed-bf16 h inline)
    lstm_fused_kernel<<<2 * NB, 256>>>(ppe, eWhh, phh, ppd, dWhh, phd);

    // 7. fcW conversion (independent of LSTM outputs)
    f2b_kernel<<<(LOC_N * FC_K / 8 + 255) / 256, 256>>>(fcW, pfcb, LOC_N * FC_K);
    // 8. attention scores = hd @ hh^T
    gemm_tc<<<dim3(SH_LEN / 128, T_LEN / 128), 256>>>(phdb, phhb, pat, nullptr, nullptr,
                                                      T_LEN, SH_LEN, H_DIM);
    // 9. softmax rows -> bf16
    softmax_kernel<<<T_LEN, 256>>>();
    // 10. context = attn @ hh  (as attn @ (hh^T)^T)
    gemm_tc<<<dim3(H_DIM / 128, T_LEN / 128), 256>>>(patb, phhTb, pcx, nullptr, nullptr,
                                                     T_LEN, H_DIM, SH_LEN);
    // 11. concat -> bf16
    concat_kernel<<<T_LEN, 272>>>(emb_uid, uid);
    // 12. FC: y = outc @ fcW^T + fcb
    gemm_tc<<<dim3((LOC_N + 127) / 128, T_LEN / 128), 256>>>(potb, pfcb, py, fcb, nullptr,
                                                             T_LEN, LOC_N, FC_K);
    // 13. log_softmax -> output
    logsoftmax_kernel<<<T_LEN, 256>>>(out);
}